// round 2
// baseline (speedup 1.0000x reference)
#include <cuda_runtime.h>
#include <math.h>

#define KNN 8
#define THREADS 128
#define TILE 2048

__global__ void zero_out_kernel(float* out) { out[0] = 0.0f; }

__global__ __launch_bounds__(THREADS)
void chamfer_knn_kernel(const float* __restrict__ src,
                        const float* __restrict__ tgt,
                        const float* __restrict__ flow,
                        float* __restrict__ out,
                        int N, float scale)
{
    __shared__ float4 sh[TILE];
    __shared__ float warp_red[THREADS / 32];

    const int dir = blockIdx.z;           // 0: pred->target, 1: target->pred
    const int b   = blockIdx.y;
    const int q   = blockIdx.x * THREADS + threadIdx.x;   // query index in [0,N)

    const float* __restrict__ srcB  = src  + (size_t)b * N * 3;
    const float* __restrict__ tgtB  = tgt  + (size_t)b * N * 3;
    const float* __restrict__ flowB = flow + (size_t)b * N * 3;

    // ---- query point ----
    float qx, qy, qz;
    if (dir == 0) {
        qx = srcB[q * 3 + 0] + flowB[q * 3 + 0];
        qy = srcB[q * 3 + 1] + flowB[q * 3 + 1];
        qz = srcB[q * 3 + 2] + flowB[q * 3 + 2];
    } else {
        qx = tgtB[q * 3 + 0];
        qy = tgtB[q * 3 + 1];
        qz = tgtB[q * 3 + 2];
    }
    const float q2 = qx * qx + qy * qy + qz * qz;

    // ---- top-8 smallest rank values r = p2 - 2*q.p  (d2 = r + q2) ----
    // Invariant: best[0] is the maximum of the 8 (the "worst" kept candidate).
    float best[KNN];
#pragma unroll
    for (int i = 0; i < KNN; i++) best[i] = 3.0e38f;
    float worst = 3.0e38f;

    for (int base = 0; base < N; base += TILE) {
        __syncthreads();
        // cooperative stage of TILE points as (x,y,z,p2)
        for (int j = threadIdx.x; j < TILE; j += THREADS) {
            const int p = base + j;
            float px, py, pz;
            if (dir == 0) {
                px = tgtB[p * 3 + 0];
                py = tgtB[p * 3 + 1];
                pz = tgtB[p * 3 + 2];
            } else {
                px = srcB[p * 3 + 0] + flowB[p * 3 + 0];
                py = srcB[p * 3 + 1] + flowB[p * 3 + 1];
                pz = srcB[p * 3 + 2] + flowB[p * 3 + 2];
            }
            sh[j] = make_float4(px, py, pz, px * px + py * py + pz * pz);
        }
        __syncthreads();

#pragma unroll 8
        for (int j = 0; j < TILE; j++) {
            const float4 p = sh[j];
            float m = qx * p.x;
            m = fmaf(qy, p.y, m);
            m = fmaf(qz, p.z, m);
            const float r = fmaf(-2.0f, m, p.w);
            if (r < worst) {
                best[0] = r;                 // replace current max
#pragma unroll
                for (int i = 1; i < KNN; i++) {
                    if (best[i] > best[0]) { float t = best[0]; best[0] = best[i]; best[i] = t; }
                }
                worst = best[0];             // best[0] is the new max
            }
        }
    }

    // ---- per-query mean distance contribution ----
    float s = 0.0f;
#pragma unroll
    for (int i = 0; i < KNN; i++)
        s += sqrtf(fmaxf(best[i] + q2, 0.0f));
    s *= scale;   // scale = 1 / (KNN * B * N) folds the /8 neighbor mean and the global mean

    // ---- block reduction: warp shuffle, then across warps ----
    const int lane = threadIdx.x & 31;
    const int wid  = threadIdx.x >> 5;
#pragma unroll
    for (int off = 16; off > 0; off >>= 1)
        s += __shfl_xor_sync(0xFFFFFFFFu, s, off);
    if (lane == 0) warp_red[wid] = s;
    __syncthreads();
    if (wid == 0) {
        float v = (lane < THREADS / 32) ? warp_red[lane] : 0.0f;
#pragma unroll
        for (int off = 16; off > 0; off >>= 1)
            v += __shfl_xor_sync(0xFFFFFFFFu, v, off);
        if (lane == 0) atomicAdd(out, v);
    }
}

extern "C" void kernel_launch(void* const* d_in, const int* in_sizes, int n_in,
                              void* d_out, int out_size)
{
    const float* src  = (const float*)d_in[0];   // pc_source [B,N,3]
    const float* tgt  = (const float*)d_in[1];   // pc_target [B,N,3]
    const float* flow = (const float*)d_in[2];   // pred_flow [B,N,3]
    float* out = (float*)d_out;

    const int N = 8192;
    const int B = in_sizes[0] / (N * 3);
    const float scale = 1.0f / ((float)KNN * (float)B * (float)N);

    zero_out_kernel<<<1, 1>>>(out);

    dim3 grid(N / THREADS, B, 2);
    chamfer_knn_kernel<<<grid, THREADS>>>(src, tgt, flow, out, N, scale);
}

// round 6
// speedup vs baseline: 1.0991x; 1.0991x over previous
#include <cuda_runtime.h>
#include <math.h>

#define KNN 8
#define THREADS 128
#define TILE 2048            // points per shared tile (32 KB packed)

__global__ void zero_out_kernel(float* out) { out[0] = 0.0f; }

// packed f32x2 fma: (d.lo,d.hi) = (a.lo*b.lo+c.lo, a.hi*b.hi+c.hi)
__device__ __forceinline__ unsigned long long ffma2(unsigned long long a,
                                                    unsigned long long b,
                                                    unsigned long long c) {
    unsigned long long d;
    asm("fma.rn.f32x2 %0, %1, %2, %3;" : "=l"(d) : "l"(a), "l"(b), "l"(c));
    return d;
}

__device__ __forceinline__ unsigned long long pack2(float lo, float hi) {
    return ((unsigned long long)__float_as_uint(hi) << 32) | __float_as_uint(lo);
}

__global__ __launch_bounds__(THREADS)
void chamfer_knn_kernel(const float* __restrict__ src,
                        const float* __restrict__ tgt,
                        const float* __restrict__ flow,
                        float* __restrict__ out,
                        int N, float scale)
{
    // pair j of points (2j, 2j+1):  sh[2j] = (x',y')  sh[2j+1] = (z',w)
    // where x' = (-2*x1, -2*x2) packed, w = (|p1|^2, |p2|^2) packed
    __shared__ ulonglong2 sh[TILE];
    __shared__ float warp_red[THREADS / 32];

    const int dir = blockIdx.z;           // 0: pred->target, 1: target->pred
    const int b   = blockIdx.y;
    const int q   = blockIdx.x * THREADS + threadIdx.x;

    const float* __restrict__ srcB  = src  + (size_t)b * N * 3;
    const float* __restrict__ tgtB  = tgt  + (size_t)b * N * 3;
    const float* __restrict__ flowB = flow + (size_t)b * N * 3;

    // ---- query point ----
    float qx, qy, qz;
    if (dir == 0) {
        qx = srcB[q * 3 + 0] + flowB[q * 3 + 0];
        qy = srcB[q * 3 + 1] + flowB[q * 3 + 1];
        qz = srcB[q * 3 + 2] + flowB[q * 3 + 2];
    } else {
        qx = tgtB[q * 3 + 0];
        qy = tgtB[q * 3 + 1];
        qz = tgtB[q * 3 + 2];
    }
    const float q2 = qx * qx + qy * qy + qz * qz;
    const unsigned long long qx2 = pack2(qx, qx);
    const unsigned long long qy2 = pack2(qy, qy);
    const unsigned long long qz2 = pack2(qz, qz);

    // ---- top-8 smallest rank values r = p2 - 2*q.p  (d2 = r + q2) ----
    // Invariant: best[0] is the maximum of the 8 kept candidates.
    float best[KNN];
#pragma unroll
    for (int i = 0; i < KNN; i++) best[i] = 3.0e38f;

    for (int base = 0; base < N; base += TILE) {
        __syncthreads();
        // cooperative stage: each staged pair = 2 consecutive points
        for (int j = threadIdx.x; j < TILE / 2; j += THREADS) {
            const int p0 = base + 2 * j;
            float x1, y1, z1, x2f, y2f, z2f;
            if (dir == 0) {
                x1  = tgtB[p0 * 3 + 0]; y1  = tgtB[p0 * 3 + 1]; z1  = tgtB[p0 * 3 + 2];
                x2f = tgtB[p0 * 3 + 3]; y2f = tgtB[p0 * 3 + 4]; z2f = tgtB[p0 * 3 + 5];
            } else {
                x1  = srcB[p0 * 3 + 0] + flowB[p0 * 3 + 0];
                y1  = srcB[p0 * 3 + 1] + flowB[p0 * 3 + 1];
                z1  = srcB[p0 * 3 + 2] + flowB[p0 * 3 + 2];
                x2f = srcB[p0 * 3 + 3] + flowB[p0 * 3 + 3];
                y2f = srcB[p0 * 3 + 4] + flowB[p0 * 3 + 4];
                z2f = srcB[p0 * 3 + 5] + flowB[p0 * 3 + 5];
            }
            const float w1 = x1 * x1 + y1 * y1 + z1 * z1;
            const float w2 = x2f * x2f + y2f * y2f + z2f * z2f;
            sh[2 * j]     = make_ulonglong2(pack2(-2.0f * x1, -2.0f * x2f),
                                            pack2(-2.0f * y1, -2.0f * y2f));
            sh[2 * j + 1] = make_ulonglong2(pack2(-2.0f * z1, -2.0f * z2f),
                                            pack2(w1, w2));
        }
        __syncthreads();

#pragma unroll 4
        for (int j = 0; j < TILE / 2; j++) {
            const ulonglong2 A = sh[2 * j];        // (x', y')
            const ulonglong2 C = sh[2 * j + 1];    // (z', w)
            unsigned long long t = ffma2(qz2, C.x, C.y);
            t = ffma2(qy2, A.y, t);
            t = ffma2(qx2, A.x, t);
            const float r1 = __uint_as_float((unsigned int)t);
            const float r2 = __uint_as_float((unsigned int)(t >> 32));

            if (r1 < best[0]) {
                best[0] = r1;
#pragma unroll
                for (int i = 1; i < KNN; i++) {
                    if (best[i] > best[0]) { float tt = best[0]; best[0] = best[i]; best[i] = tt; }
                }
            }
            if (r2 < best[0]) {
                best[0] = r2;
#pragma unroll
                for (int i = 1; i < KNN; i++) {
                    if (best[i] > best[0]) { float tt = best[0]; best[0] = best[i]; best[i] = tt; }
                }
            }
        }
    }

    // ---- per-query mean distance contribution ----
    float s = 0.0f;
#pragma unroll
    for (int i = 0; i < KNN; i++)
        s += sqrtf(fmaxf(best[i] + q2, 0.0f));
    s *= scale;   // 1 / (KNN * B * N) folds neighbor mean and global mean

    // ---- block reduction ----
    const int lane = threadIdx.x & 31;
    const int wid  = threadIdx.x >> 5;
#pragma unroll
    for (int off = 16; off > 0; off >>= 1)
        s += __shfl_xor_sync(0xFFFFFFFFu, s, off);
    if (lane == 0) warp_red[wid] = s;
    __syncthreads();
    if (wid == 0) {
        float v = (lane < THREADS / 32) ? warp_red[lane] : 0.0f;
#pragma unroll
        for (int off = 16; off > 0; off >>= 1)
            v += __shfl_xor_sync(0xFFFFFFFFu, v, off);
        if (lane == 0) atomicAdd(out, v);
    }
}

extern "C" void kernel_launch(void* const* d_in, const int* in_sizes, int n_in,
                              void* d_out, int out_size)
{
    const float* src  = (const float*)d_in[0];   // pc_source [B,N,3]
    const float* tgt  = (const float*)d_in[1];   // pc_target [B,N,3]
    const float* flow = (const float*)d_in[2];   // pred_flow [B,N,3]
    float* out = (float*)d_out;

    const int N = 8192;
    const int B = in_sizes[0] / (N * 3);
    const float scale = 1.0f / ((float)KNN * (float)B * (float)N);

    zero_out_kernel<<<1, 1>>>(out);

    dim3 grid(N / THREADS, B, 2);
    chamfer_knn_kernel<<<grid, THREADS>>>(src, tgt, flow, out, N, scale);
}